// round 12
// baseline (speedup 1.0000x reference)
#include <cuda_runtime.h>

#define BATCH 131072
#define NCH 16
#define NK 15
#define NZ 256
#define NCOUT 10
#define MAXREG 128
#define VOCAB 1024

typedef unsigned long long u64;

// ---------------- scratch (device globals; no allocation) ----------------
__device__ unsigned       g_seen[NCH][1024];     // built by k_masks (RED.OR), read+zeroed by k_tables
__device__ unsigned char  g_rmap[NCH][32768];    // mask -> region id (observed entries valid this launch)
__device__ unsigned       g_maskw[BATCH * 8];    // packed masks: channel pair per u32
__device__ int            g_cnt[NCH];            // #distinct masks per channel (<=121)
__device__ float          g_zreg[NCH][MAXREG][NZ];       // per-region half z-row
__device__ unsigned char  g_cross[8][MAXREG][MAXREG];    // argmax index per (c8, rA, rB)

// ================= K1: sign masks — filterless, fire-and-forget RED.OR ==================
// 19.3 KB smem -> high residency; global atomics issued no-return (no warp stall);
// L2-side OR serialization overlaps with compute.
#define K1_BLK 256
#define K1_THR 512
#define K1_SMEM (8192 + 8192 + 1920 + 960)   // 19264 B

__global__ void __launch_bounds__(K1_THR, 2) k_masks(
    const int* __restrict__ x, const float* __restrict__ lenLUT,
    const float* __restrict__ ipdLUT, const float* __restrict__ S,
    const float* __restrict__ T)
{
    extern __shared__ char dyn[];
    float2*     sLen = (float2*)dyn;                     // 8 KB
    float2*     sIpd = (float2*)(dyn + 8192);            // 8 KB
    ulonglong2* sSP  = (ulonglong2*)(dyn + 16384);       // 120 x {S0p, S1p} (1920 B)
    u64*        sC   = (u64*)(dyn + 16384 + 1920);       // 120 x packed (-T-1e-4) (960 B)

    const int tid = threadIdx.x;
    for (int i = tid; i < VOCAB; i += K1_THR) {
        sLen[i] = ((const float2*)lenLUT)[i];
        sIpd[i] = ((const float2*)ipdLUT)[i];
    }
    if (tid < 120) {                                     // pack per-pair plane constants
        int i = tid / NK, k = tid % NK;
        int cA = 2 * i, cB = 2 * i + 1;
        u64 s0 = ((u64)__float_as_uint(S[cB * 30 + k])      << 32) | __float_as_uint(S[cA * 30 + k]);
        u64 s1 = ((u64)__float_as_uint(S[cB * 30 + 15 + k]) << 32) | __float_as_uint(S[cA * 30 + 15 + k]);
        float cAv = -T[cA * NK + k] - 1e-4f;
        float cBv = -T[cB * NK + k] - 1e-4f;
        sSP[tid] = make_ulonglong2(s0, s1);
        sC[tid]  = ((u64)__float_as_uint(cBv) << 32) | __float_as_uint(cAv);
    }
    __syncthreads();

    const int b = blockIdx.x * K1_THR + tid;             // exact cover: 256*512 = BATCH
    const int4* xp = (const int4*)x + (size_t)b * 8;

    unsigned words[8];
    #pragma unroll
    for (int i = 0; i < 8; i++) {
        int4   xv = __ldg(&xp[i]);
        float2 lA = sLen[xv.x], pA = sIpd[xv.y];
        float2 lB = sLen[xv.z], pB = sIpd[xv.w];
        float e0A = lA.x + pA.x, e1A = lA.y + pA.y;
        float e0B = lB.x + pB.x, e1B = lB.y + pB.y;
        u64 e0p, e1p;
        asm("mov.b64 %0, {%1, %2};" : "=l"(e0p) : "f"(e0A), "f"(e0B));
        asm("mov.b64 %0, {%1, %2};" : "=l"(e1p) : "f"(e1A), "f"(e1B));
        unsigned pair = 0;
        #pragma unroll
        for (int k = 0; k < NK; k++) {
            ulonglong2 sp = sSP[i * NK + k];             // LDS.128 (uniform -> broadcast)
            u64        cc = sC[i * NK + k];              // LDS.64
            u64 t2, y2;
            asm("fma.rn.f32x2 %0, %1, %2, %3;" : "=l"(t2) : "l"(e0p), "l"(sp.x), "l"(cc));
            asm("fma.rn.f32x2 %0, %1, %2, %3;" : "=l"(y2) : "l"(e1p), "l"(sp.y), "l"(t2));
            unsigned lo = (unsigned)y2;
            unsigned hi = (unsigned)(y2 >> 32);
            pair |= ((lo >> 31) << k) | ((hi >> 31) << (16 + k));   // bit set <=> y<0
        }
        words[i] = pair;
        // fire-and-forget observation (RED.OR, no return value -> no warp stall)
        atomicOr(&g_seen[2 * i    ][(pair & 0xffffu) >> 5], 1u << (pair & 31));
        atomicOr(&g_seen[2 * i + 1][(pair >> 16) >> 5],     1u << ((pair >> 16) & 31));
    }

    uint4* mp = (uint4*)&g_maskw[(size_t)b * 8];
    mp[0] = make_uint4(words[0], words[1], words[2], words[3]);
    mp[1] = make_uint4(words[4], words[5], words[6], words[7]);
}

// ================= K2: dedup + global region map + self-clean + zreg =================
__global__ void __launch_bounds__(1024) k_tables(const float* __restrict__ H) {  // <<<16, 1024>>>
    const int c = blockIdx.x, tid = threadIdx.x;
    __shared__ int            sc[256];
    __shared__ unsigned short sMask[MAXREG];
    __shared__ float          sH[NK][NZ];
    __shared__ int            s_cnt;

    unsigned w[4]; int pc = 0;
    if (tid < 256) {
        #pragma unroll
        for (int j = 0; j < 4; j++) {
            w[j] = g_seen[c][tid * 4 + j];
            g_seen[c][tid * 4 + j] = 0u;               // self-clean for next launch
            pc += __popc(w[j]);
        }
        sc[tid] = pc;
    }
    const int base = (c & 1) * NK;                     // even ch -> H rows 0..14, odd -> 15..29
    for (int i = tid; i < NK * NZ; i += 1024)
        sH[i >> 8][i & 255] = H[(base + (i >> 8)) * NZ + (i & 255)];
    __syncthreads();
    for (int off = 1; off < 256; off <<= 1) {          // Hillis-Steele inclusive scan (256 lanes)
        int v = 0;
        if (tid < 256 && tid >= off) v = sc[tid - off];
        __syncthreads();
        if (tid < 256) sc[tid] += v;
        __syncthreads();
    }
    if (tid < 256) {
        int id = sc[tid] - pc;                         // exclusive prefix (ascending-mask order)
        if (tid == 255) { g_cnt[c] = min(sc[255], MAXREG); s_cnt = min(sc[255], MAXREG); }
        #pragma unroll
        for (int j = 0; j < 4; j++) {
            const int word = tid * 4 + j;
            unsigned ww = w[j];
            const unsigned mb = (unsigned)word << 5;
            while (ww) {
                int bb = __ffs(ww) - 1; ww &= ww - 1;
                if (id < MAXREG) {
                    unsigned short mask = (unsigned short)(mb | (unsigned)bb);
                    g_rmap[c][mask] = (unsigned char)id;   // global mask -> region id
                    sMask[id] = mask;
                }
                id++;
            }
        }
    }
    __syncthreads();

    const int cnt = s_cnt;
    const int col = tid & 255, grp = tid >> 8;         // 4-way row parallelism
    for (int r = grp; r < cnt; r += 4) {
        unsigned m = sMask[r];
        float acc = 0.f;
        #pragma unroll
        for (int d = 0; d < NK; d++) {
            float hv = sH[d][col];
            acc += ((m >> d) & 1) ? -hv : hv;
        }
        g_zreg[c][r][col] = acc;
    }
}

// ================= K3: argmax table, rA tiled x4 (shuffle version) =================
__global__ void k_cross() {   // <<<dim3(32, 8), 256>>>
    const int c8 = blockIdx.y, rAt = blockIdx.x;
    const int cA = 2 * c8, cB = cA + 1;
    const int nA = g_cnt[cA], nB = g_cnt[cB];
    const int rA0 = rAt * 4;
    if (rA0 >= nA) return;
    const int na = min(4, nA - rA0);
    __shared__ float zA[4][NZ];
    for (int i = threadIdx.x; i < 4 * NZ; i += 256) {
        int rr = i >> 8, k = i & 255;
        zA[rr][k] = (rr < na) ? g_zreg[cA][rA0 + rr][k] : 0.f;
    }
    __syncthreads();
    const int warp = threadIdx.x >> 5, lane = threadIdx.x & 31;
    for (int rB = warp; rB < nB; rB += 8) {
        const float* zb = &g_zreg[cB][rB][0];
        float zl[8];
        #pragma unroll
        for (int j = 0; j < 8; j++) zl[j] = zb[j * 32 + lane];
        #pragma unroll
        for (int i2 = 0; i2 < 4; i2++) {
            float best = __int_as_float(0xff800000);  // -inf
            int   bk = 0;
            #pragma unroll
            for (int j = 0; j < 8; j++) {
                int k = j * 32 + lane;                // ascending per lane
                float v = zA[i2][k] + zl[j];
                if (v > best) { best = v; bk = k; }
            }
            #pragma unroll
            for (int off = 16; off; off >>= 1) {      // first-index-wins warp argmax
                float ov = __shfl_down_sync(0xffffffffu, best, off);
                int   ok = __shfl_down_sync(0xffffffffu, bk, off);
                if (ov > best || (ov == best && ok < bk)) { best = ov; bk = ok; }
            }
            if (lane == 0 && i2 < na) g_cross[c8][rA0 + i2][rB] = (unsigned char)bk;
        }
    }
}

// ================= K4: gather (L2 rmap/cross + smem LUT) + log_softmax =================
#define K4_BLK 256
#define K4_THR 512
#define LUTPAD 12
#define K4_SMEM (8 * 256 * LUTPAD * 4)   // 98304 B -> 2 blocks/SM

__global__ void __launch_bounds__(K4_THR, 2) k_main(
    const float* __restrict__ LUT, float* __restrict__ out)
{
    extern __shared__ char dyn[];
    float* slut = (float*)dyn;

    const int tid = threadIdx.x;
    for (int row = tid; row < 8 * 256; row += K4_THR) {
        #pragma unroll
        for (int j = 0; j < LUTPAD; j++)
            slut[row * LUTPAD + j] = (j < NCOUT) ? LUT[row * NCOUT + j] : 0.f;
    }
    __syncthreads();

    const int b = blockIdx.x * K4_THR + tid;             // exact cover: 256*512 = BATCH
    const uint4* mp = (const uint4*)&g_maskw[(size_t)b * 8];
    uint4 m0 = mp[0], m1 = mp[1];
    unsigned mw[8] = {m0.x, m0.y, m0.z, m0.w, m1.x, m1.y, m1.z, m1.w};

    int r[NCH];
    #pragma unroll
    for (int i = 0; i < 8; i++) {                        // 16 independent L2 u8 loads
        r[2 * i]     = __ldg(&g_rmap[2 * i][mw[i] & 0xffffu]);
        r[2 * i + 1] = __ldg(&g_rmap[2 * i + 1][mw[i] >> 16]);
    }

    int idx[8];
    #pragma unroll
    for (int c8 = 0; c8 < 8; c8++)                       // 8 independent L2 u8 loads
        idx[c8] = __ldg(&g_cross[c8][r[2 * c8]][r[2 * c8 + 1]]);

    float4 a0 = make_float4(0.f, 0.f, 0.f, 0.f), a1 = a0, a2 = a0;
    #pragma unroll
    for (int c8 = 0; c8 < 8; c8++) {
        const float4* p = (const float4*)&slut[(c8 * 256 + idx[c8]) * LUTPAD];
        float4 v0 = p[0], v1 = p[1], v2 = p[2];
        a0.x += v0.x; a0.y += v0.y; a0.z += v0.z; a0.w += v0.w;
        a1.x += v1.x; a1.y += v1.y; a1.z += v1.z; a1.w += v1.w;
        a2.x += v2.x; a2.y += v2.y;                      // lanes 10,11 are pad
    }
    float acc[NCOUT] = {a0.x, a0.y, a0.z, a0.w, a1.x, a1.y, a1.z, a1.w, a2.x, a2.y};

    float mx = acc[0];
    #pragma unroll
    for (int j = 1; j < NCOUT; j++) mx = fmaxf(mx, acc[j]);
    float s = 0.f;
    #pragma unroll
    for (int j = 0; j < NCOUT; j++) s += __expf(acc[j] - mx);
    float lg = __logf(s);

    float2* op = (float2*)(out + (size_t)b * NCOUT);
    #pragma unroll
    for (int j = 0; j < 5; j++)
        op[j] = make_float2((acc[2 * j] - mx) - lg, (acc[2 * j + 1] - mx) - lg);
}

// ---------------- launch ----------------
extern "C" void kernel_launch(void* const* d_in, const int* in_sizes, int n_in,
                              void* d_out, int out_size) {
    const int*   x      = (const int*)d_in[0];
    const float* lenLUT = (const float*)d_in[1];
    const float* ipdLUT = (const float*)d_in[2];
    const float* S      = (const float*)d_in[3];
    const float* H      = (const float*)d_in[4];
    const float* T      = (const float*)d_in[5];
    const float* LUT    = (const float*)d_in[6];
    float*       out    = (float*)d_out;

    static int attr_done = 0;   // host-side, idempotent (set on the pre-capture correctness call)
    if (!attr_done) {
        cudaFuncSetAttribute(k_masks, cudaFuncAttributeMaxDynamicSharedMemorySize, K1_SMEM);
        cudaFuncSetAttribute(k_main,  cudaFuncAttributeMaxDynamicSharedMemorySize, K4_SMEM);
        // uniform carveout across ALL kernels: avoid inter-kernel smem/L1 repartition drains
        cudaFuncSetAttribute(k_masks,  cudaFuncAttributePreferredSharedMemoryCarveout, 100);
        cudaFuncSetAttribute(k_tables, cudaFuncAttributePreferredSharedMemoryCarveout, 100);
        cudaFuncSetAttribute(k_cross,  cudaFuncAttributePreferredSharedMemoryCarveout, 100);
        cudaFuncSetAttribute(k_main,   cudaFuncAttributePreferredSharedMemoryCarveout, 100);
        attr_done = 1;
    }

    k_masks <<<K1_BLK, K1_THR, K1_SMEM>>>(x, lenLUT, ipdLUT, S, T);
    k_tables<<<16, 1024>>>(H);
    k_cross <<<dim3(32, 8), 256>>>();
    k_main  <<<K4_BLK, K4_THR, K4_SMEM>>>(LUT, out);
}

// round 13
// speedup vs baseline: 2.1150x; 2.1150x over previous
#include <cuda_runtime.h>

#define BATCH 131072
#define NCH 16
#define NK 15
#define NZ 256
#define NCOUT 10
#define MAXREG 128
#define VOCAB 1024

typedef unsigned long long u64;

// ---------------- scratch (device globals; no allocation) ----------------
__device__ unsigned       g_seen[NCH][1024];     // built by k_masks, read+zeroed by k_tc tables blocks
__device__ unsigned char  g_rmap[NCH][32768];    // mask -> region id (observed entries valid this launch)
__device__ unsigned       g_maskw[BATCH * 8];    // packed masks: channel pair per u32
__device__ int            g_cnt[NCH];            // #distinct masks per channel (<=121)
__device__ float          g_zreg[NCH][MAXREG][NZ];       // per-region half z-row
__device__ unsigned char  g_cross[8][MAXREG][MAXREG];    // argmax index per (c8, rA, rB)
__device__ volatile int   g_flag[NCH];           // per-channel tables-done; reset by k_main

// ================= K1: sign masks — 2 elements/thread, constants amortized (R11) ========
#define K1_BLK 256
#define K1_THR 256
#define K1_SMEM (8192 + 8192 + 1920 + 960 + 65536)   // 84800 B -> 2 blocks/SM

__global__ void __launch_bounds__(K1_THR, 2) k_masks(
    const int* __restrict__ x, const float* __restrict__ lenLUT,
    const float* __restrict__ ipdLUT, const float* __restrict__ S,
    const float* __restrict__ T)
{
    extern __shared__ char dyn[];
    float2*     sLen = (float2*)dyn;                     // 8 KB
    float2*     sIpd = (float2*)(dyn + 8192);            // 8 KB
    ulonglong2* sSP  = (ulonglong2*)(dyn + 16384);       // 120 x {S0p, S1p}  (1920 B)
    u64*        sC   = (u64*)(dyn + 16384 + 1920);       // 120 x packed (-T-1e-4) (960 B)
    unsigned*   filt = (unsigned*)(dyn + 16384 + 2880);  // 64 KB block-local seen filter

    const int tid = threadIdx.x;
    for (int i = tid; i < VOCAB; i += K1_THR) {
        sLen[i] = ((const float2*)lenLUT)[i];
        sIpd[i] = ((const float2*)ipdLUT)[i];
    }
    if (tid < 120) {                                     // pack per-pair plane constants
        int i = tid / NK, k = tid % NK;
        int cA = 2 * i, cB = 2 * i + 1;
        u64 s0 = ((u64)__float_as_uint(S[cB * 30 + k])      << 32) | __float_as_uint(S[cA * 30 + k]);
        u64 s1 = ((u64)__float_as_uint(S[cB * 30 + 15 + k]) << 32) | __float_as_uint(S[cA * 30 + 15 + k]);
        float cAv = -T[cA * NK + k] - 1e-4f;
        float cBv = -T[cB * NK + k] - 1e-4f;
        sSP[tid] = make_ulonglong2(s0, s1);
        sC[tid]  = ((u64)__float_as_uint(cBv) << 32) | __float_as_uint(cAv);
    }
    for (int i = tid; i < NCH * 1024; i += K1_THR) filt[i] = 0u;
    __syncthreads();

    const int b0 = blockIdx.x * K1_THR + tid;            // 65536 threads, 2 elems each
    const int b1 = b0 + 65536;
    const int4* xp0 = (const int4*)x + (size_t)b0 * 8;
    const int4* xp1 = (const int4*)x + (size_t)b1 * 8;

    unsigned w0[8], w1[8];
    #pragma unroll
    for (int i = 0; i < 8; i++) {
        int4 xv0 = __ldg(&xp0[i]);
        int4 xv1 = __ldg(&xp1[i]);

        float2 lA0 = sLen[xv0.x], pA0 = sIpd[xv0.y];
        float2 lB0 = sLen[xv0.z], pB0 = sIpd[xv0.w];
        float2 lA1 = sLen[xv1.x], pA1 = sIpd[xv1.y];
        float2 lB1 = sLen[xv1.z], pB1 = sIpd[xv1.w];

        u64 e0p0, e1p0, e0p1, e1p1;
        {
            float a = lA0.x + pA0.x, b = lB0.x + pB0.x;
            asm("mov.b64 %0, {%1, %2};" : "=l"(e0p0) : "f"(a), "f"(b));
            float c = lA0.y + pA0.y, d = lB0.y + pB0.y;
            asm("mov.b64 %0, {%1, %2};" : "=l"(e1p0) : "f"(c), "f"(d));
            float e = lA1.x + pA1.x, f = lB1.x + pB1.x;
            asm("mov.b64 %0, {%1, %2};" : "=l"(e0p1) : "f"(e), "f"(f));
            float g = lA1.y + pA1.y, h = lB1.y + pB1.y;
            asm("mov.b64 %0, {%1, %2};" : "=l"(e1p1) : "f"(g), "f"(h));
        }

        unsigned pair0 = 0, pair1 = 0;
        #pragma unroll
        for (int k = 0; k < NK; k++) {
            ulonglong2 sp = sSP[i * NK + k];             // LDS.128: S0p, S1p
            u64        cc = sC[i * NK + k];              // LDS.64
            u64 t0, y0, t1, y1;
            asm("fma.rn.f32x2 %0, %1, %2, %3;" : "=l"(t0) : "l"(e0p0), "l"(sp.x), "l"(cc));
            asm("fma.rn.f32x2 %0, %1, %2, %3;" : "=l"(t1) : "l"(e0p1), "l"(sp.x), "l"(cc));
            asm("fma.rn.f32x2 %0, %1, %2, %3;" : "=l"(y0) : "l"(e1p0), "l"(sp.y), "l"(t0));
            asm("fma.rn.f32x2 %0, %1, %2, %3;" : "=l"(y1) : "l"(e1p1), "l"(sp.y), "l"(t1));
            unsigned lo0 = (unsigned)y0, hi0 = (unsigned)(y0 >> 32);
            unsigned lo1 = (unsigned)y1, hi1 = (unsigned)(y1 >> 32);
            pair0 |= ((lo0 >> 31) << k) | ((hi0 >> 31) << (16 + k));  // bit set <=> y<0
            pair1 |= ((lo1 >> 31) << k) | ((hi1 >> 31) << (16 + k));
        }
        w0[i] = pair0;
        w1[i] = pair1;
    }

    {
        uint4* mp0 = (uint4*)&g_maskw[(size_t)b0 * 8];
        mp0[0] = make_uint4(w0[0], w0[1], w0[2], w0[3]);
        mp0[1] = make_uint4(w0[4], w0[5], w0[6], w0[7]);
        uint4* mp1 = (uint4*)&g_maskw[(size_t)b1 * 8];
        mp1[0] = make_uint4(w1[0], w1[1], w1[2], w1[3]);
        mp1[1] = make_uint4(w1[4], w1[5], w1[6], w1[7]);
    }

    // seen-set update for both elements (block filter -> rare global atomic)
    #pragma unroll
    for (int i = 0; i < 8; i++) {
        #pragma unroll
        for (int h = 0; h < 2; h++) {
            unsigned m0 = (w0[i] >> (16 * h)) & 0xffffu;
            unsigned m1 = (w1[i] >> (16 * h)) & 0xffffu;
            int c = 2 * i + h;
            unsigned wd0 = c * 1024 + (m0 >> 5), bt0 = 1u << (m0 & 31);
            if (!(filt[wd0] & bt0)) {
                unsigned old = atomicOr(&filt[wd0], bt0);
                if (!(old & bt0)) atomicOr((unsigned*)&g_seen[c][m0 >> 5], bt0);
            }
            unsigned wd1 = c * 1024 + (m1 >> 5), bt1 = 1u << (m1 & 31);
            if (!(filt[wd1] & bt1)) {
                unsigned old = atomicOr(&filt[wd1], bt1);
                if (!(old & bt1)) atomicOr((unsigned*)&g_seen[c][m1 >> 5], bt1);
            }
        }
    }
}

// ================= K2: fused tables + cross. blocks 0-15 = tables(channel c);
// blocks 16-271 = cross, spinning on g_flag for exactly their two channels.
// Deadlock-free: 272 blocks x 1024 thr all resident (2 blocks/SM x 148 SMs = 296 slots).
__global__ void __launch_bounds__(1024, 2) k_tc(const float* __restrict__ H) {  // <<<272, 1024>>>
    const int tid = threadIdx.x;

    __shared__ union {
        struct {                                   // tables path
            int            sc[256];
            unsigned short sMask[MAXREG];
            float          sH[NK][NZ];
            int            s_cnt;
        } t;
        struct {                                   // cross path
            float zA[4][NZ];
        } x;
    } sh;

    if (blockIdx.x < NCH) {
        // ---------------- tables: dedup + rmap + self-clean + zreg ----------------
        const int c = blockIdx.x;
        unsigned w[4]; int pc = 0;
        if (tid < 256) {
            #pragma unroll
            for (int j = 0; j < 4; j++) {
                w[j] = g_seen[c][tid * 4 + j];
                g_seen[c][tid * 4 + j] = 0u;               // self-clean for next launch
                pc += __popc(w[j]);
            }
            sh.t.sc[tid] = pc;
        }
        const int base = (c & 1) * NK;                     // even ch -> H rows 0..14, odd -> 15..29
        for (int i = tid; i < NK * NZ; i += 1024)
            sh.t.sH[i >> 8][i & 255] = H[(base + (i >> 8)) * NZ + (i & 255)];
        __syncthreads();
        for (int off = 1; off < 256; off <<= 1) {          // Hillis-Steele inclusive scan
            int v = 0;
            if (tid < 256 && tid >= off) v = sh.t.sc[tid - off];
            __syncthreads();
            if (tid < 256) sh.t.sc[tid] += v;
            __syncthreads();
        }
        if (tid < 256) {
            int id = sh.t.sc[tid] - pc;                    // exclusive prefix (ascending-mask order)
            if (tid == 255) { g_cnt[c] = min(sh.t.sc[255], MAXREG); sh.t.s_cnt = min(sh.t.sc[255], MAXREG); }
            #pragma unroll
            for (int j = 0; j < 4; j++) {
                const int word = tid * 4 + j;
                unsigned ww = w[j];
                const unsigned mb = (unsigned)word << 5;
                while (ww) {
                    int bb = __ffs(ww) - 1; ww &= ww - 1;
                    if (id < MAXREG) {
                        unsigned short mask = (unsigned short)(mb | (unsigned)bb);
                        g_rmap[c][mask] = (unsigned char)id;
                        sh.t.sMask[id] = mask;
                    }
                    id++;
                }
            }
        }
        __syncthreads();

        const int cnt = sh.t.s_cnt;
        const int col = tid & 255, grp = tid >> 8;         // 4-way row parallelism
        for (int r = grp; r < cnt; r += 4) {
            unsigned m = sh.t.sMask[r];
            float acc = 0.f;
            #pragma unroll
            for (int d = 0; d < NK; d++) {
                float hv = sh.t.sH[d][col];
                acc += ((m >> d) & 1) ? -hv : hv;
            }
            g_zreg[c][r][col] = acc;
        }

        // publish: all zreg/rmap/cnt writes drained, then set ready flag
        __syncthreads();
        __threadfence();
        if (tid == 0) g_flag[c] = 1;
    } else {
        // ---------------- cross: argmax table for pair c8, rA tile rAt ----------------
        const int idx2 = blockIdx.x - NCH;                 // 0..255
        const int rAt = idx2 & 31;                         // 32 rA tiles of 4
        const int c8  = idx2 >> 5;                         // 8 pairs
        const int cA = 2 * c8, cB = cA + 1;

        if (tid == 0) {                                    // wait for this pair's tables blocks
            while (!(g_flag[cA] && g_flag[cB])) __nanosleep(64);
        }
        __syncthreads();                                   // acquire for the whole block

        const int nA = g_cnt[cA], nB = g_cnt[cB];
        const int rA0 = rAt * 4;
        if (rA0 >= nA) return;
        const int na = min(4, nA - rA0);
        for (int i = tid; i < 4 * NZ; i += 1024) {
            int rr = i >> 8, k = i & 255;
            sh.x.zA[rr][k] = (rr < na) ? g_zreg[cA][rA0 + rr][k] : 0.f;
        }
        __syncthreads();
        const int warp = tid >> 5, lane = tid & 31;        // 32 warps over rB
        for (int rB = warp; rB < nB; rB += 32) {
            const float* zb = &g_zreg[cB][rB][0];
            float zl[8];
            #pragma unroll
            for (int j = 0; j < 8; j++) zl[j] = zb[j * 32 + lane];
            #pragma unroll
            for (int i2 = 0; i2 < 4; i2++) {
                float best = __int_as_float(0xff800000);   // -inf
                int   bk = 0;
                #pragma unroll
                for (int j = 0; j < 8; j++) {
                    int k = j * 32 + lane;                 // ascending per lane
                    float v = sh.x.zA[i2][k] + zl[j];
                    if (v > best) { best = v; bk = k; }
                }
                #pragma unroll
                for (int off = 16; off; off >>= 1) {       // first-index-wins warp argmax
                    float ov = __shfl_down_sync(0xffffffffu, best, off);
                    int   ok = __shfl_down_sync(0xffffffffu, bk, off);
                    if (ov > best || (ov == best && ok < bk)) { best = ov; bk = ok; }
                }
                if (lane == 0 && i2 < na) g_cross[c8][rA0 + i2][rB] = (unsigned char)bk;
            }
        }
    }
}

// ================= K3: gather (L2 rmap/cross + smem LUT) + log_softmax =================
#define K4_BLK 256
#define K4_THR 512
#define LUTPAD 12
#define K4_SMEM (8 * 256 * LUTPAD * 4)   // 98304 B -> 2 blocks/SM

__global__ void __launch_bounds__(K4_THR, 2) k_main(
    const float* __restrict__ LUT, float* __restrict__ out)
{
    extern __shared__ char dyn[];
    float* slut = (float*)dyn;

    const int tid = threadIdx.x;
    if (blockIdx.x == 0 && tid < NCH) g_flag[tid] = 0;   // reset flags for next launch
    for (int row = tid; row < 8 * 256; row += K4_THR) {
        #pragma unroll
        for (int j = 0; j < LUTPAD; j++)
            slut[row * LUTPAD + j] = (j < NCOUT) ? LUT[row * NCOUT + j] : 0.f;
    }
    __syncthreads();

    const int b = blockIdx.x * K4_THR + tid;             // exact cover: 256*512 = BATCH
    const uint4* mp = (const uint4*)&g_maskw[(size_t)b * 8];
    uint4 m0 = mp[0], m1 = mp[1];
    unsigned mw[8] = {m0.x, m0.y, m0.z, m0.w, m1.x, m1.y, m1.z, m1.w};

    int r[NCH];
    #pragma unroll
    for (int i = 0; i < 8; i++) {                        // 16 independent L2 u8 loads
        r[2 * i]     = __ldg(&g_rmap[2 * i][mw[i] & 0xffffu]);
        r[2 * i + 1] = __ldg(&g_rmap[2 * i + 1][mw[i] >> 16]);
    }

    int idx[8];
    #pragma unroll
    for (int c8 = 0; c8 < 8; c8++)                       // 8 independent L2 u8 loads
        idx[c8] = __ldg(&g_cross[c8][r[2 * c8]][r[2 * c8 + 1]]);

    float4 a0 = make_float4(0.f, 0.f, 0.f, 0.f), a1 = a0, a2 = a0;
    #pragma unroll
    for (int c8 = 0; c8 < 8; c8++) {
        const float4* p = (const float4*)&slut[(c8 * 256 + idx[c8]) * LUTPAD];
        float4 v0 = p[0], v1 = p[1], v2 = p[2];
        a0.x += v0.x; a0.y += v0.y; a0.z += v0.z; a0.w += v0.w;
        a1.x += v1.x; a1.y += v1.y; a1.z += v1.z; a1.w += v1.w;
        a2.x += v2.x; a2.y += v2.y;                      // lanes 10,11 are pad
    }
    float acc[NCOUT] = {a0.x, a0.y, a0.z, a0.w, a1.x, a1.y, a1.z, a1.w, a2.x, a2.y};

    float mx = acc[0];
    #pragma unroll
    for (int j = 1; j < NCOUT; j++) mx = fmaxf(mx, acc[j]);
    float s = 0.f;
    #pragma unroll
    for (int j = 0; j < NCOUT; j++) s += __expf(acc[j] - mx);
    float lg = __logf(s);

    float2* op = (float2*)(out + (size_t)b * NCOUT);
    #pragma unroll
    for (int j = 0; j < 5; j++)
        op[j] = make_float2((acc[2 * j] - mx) - lg, (acc[2 * j + 1] - mx) - lg);
}

// ---------------- launch ----------------
extern "C" void kernel_launch(void* const* d_in, const int* in_sizes, int n_in,
                              void* d_out, int out_size) {
    const int*   x      = (const int*)d_in[0];
    const float* lenLUT = (const float*)d_in[1];
    const float* ipdLUT = (const float*)d_in[2];
    const float* S      = (const float*)d_in[3];
    const float* H      = (const float*)d_in[4];
    const float* T      = (const float*)d_in[5];
    const float* LUT    = (const float*)d_in[6];
    float*       out    = (float*)d_out;

    static int attr_done = 0;   // host-side, idempotent (set on the pre-capture correctness call)
    if (!attr_done) {
        cudaFuncSetAttribute(k_masks, cudaFuncAttributeMaxDynamicSharedMemorySize, K1_SMEM);
        cudaFuncSetAttribute(k_main,  cudaFuncAttributeMaxDynamicSharedMemorySize, K4_SMEM);
        attr_done = 1;
    }

    k_masks<<<K1_BLK, K1_THR, K1_SMEM>>>(x, lenLUT, ipdLUT, S, T);
    k_tc   <<<NCH + 256, 1024>>>(H);
    k_main <<<K4_BLK, K4_THR, K4_SMEM>>>(LUT, out);
}